// round 2
// baseline (speedup 1.0000x reference)
#include <cuda_runtime.h>
#include <math.h>

#define BB 2
#define TT 1024
#define DD 1024
#define NH 16
#define HDIM 64
#define NL 6
#define VV 50257
#define FF (4*DD)
#define LNEPS 1e-5f
#define BT (BB*TT)

// ---------------- scratch (device globals: allocation-free rule) ----------------
__device__ float g_x  [BT*DD];
__device__ float g_h  [BT*DD];
__device__ float g_q  [BT*DD];
__device__ float g_k  [BT*DD];
__device__ float g_v  [BT*DD];
__device__ float g_att[BT*DD];
__device__ float g_ff [BT*FF];
__device__ float g_sc [(long)BB*NH*TT*TT];

// ---------------- reductions ----------------
__device__ __forceinline__ float warpSum(float v){
#pragma unroll
  for (int o=16;o;o>>=1) v += __shfl_xor_sync(0xffffffffu, v, o);
  return v;
}
__device__ __forceinline__ float warpMax(float v){
#pragma unroll
  for (int o=16;o;o>>=1) v = fmaxf(v, __shfl_xor_sync(0xffffffffu, v, o));
  return v;
}
__device__ float blockSum(float v){
  __shared__ float sh[8];
  __syncthreads();
  int lane = threadIdx.x & 31, w = threadIdx.x >> 5;
  v = warpSum(v);
  if (lane == 0) sh[w] = v;
  __syncthreads();
  if (w == 0) {
    v = (lane < (int)(blockDim.x>>5)) ? sh[lane] : 0.f;
    v = warpSum(v);
    if (lane == 0) sh[0] = v;
  }
  __syncthreads();
  return sh[0];
}
__device__ float blockMax(float v){
  __shared__ float sh[8];
  __syncthreads();
  int lane = threadIdx.x & 31, w = threadIdx.x >> 5;
  v = warpMax(v);
  if (lane == 0) sh[w] = v;
  __syncthreads();
  if (w == 0) {
    v = (lane < (int)(blockDim.x>>5)) ? sh[lane] : -3.0e38f;
    v = warpMax(v);
    if (lane == 0) sh[0] = v;
  }
  __syncthreads();
  return sh[0];
}

// ---------------- embed ----------------
__global__ void embed_kernel(const int* __restrict__ idx,
                             const float* __restrict__ tokW,
                             const float* __restrict__ posW,
                             float* __restrict__ x){
  int i = blockIdx.x;            // 0..BT-1
  int t = i % TT;
  long tok = idx[i];
  const float* tw = tokW + tok*DD;
  const float* pw = posW + (long)t*DD;
  float* xr = x + (long)i*DD;
  for (int d = threadIdx.x; d < DD; d += blockDim.x)
    xr[d] = tw[d] + pw[d];
}

// ---------------- layernorm ----------------
__global__ void ln_kernel(const float* __restrict__ x, float* __restrict__ y,
                          const float* __restrict__ g, const float* __restrict__ b){
  int row = blockIdx.x;
  const float* xr = x + (long)row*DD;
  float s = 0.f, ss = 0.f;
  for (int d = threadIdx.x; d < DD; d += blockDim.x){
    float v = xr[d]; s += v; ss += v*v;
  }
  s = blockSum(s);
  ss = blockSum(ss);
  float mean = s * (1.f/DD);
  float var  = ss * (1.f/DD) - mean*mean;
  float rstd = rsqrtf(var + LNEPS);
  float* yr = y + (long)row*DD;
  for (int d = threadIdx.x; d < DD; d += blockDim.x)
    yr[d] = (xr[d] - mean) * rstd * g[d] + b[d];
}

// ---------------- causal softmax (in place on scores) ----------------
__global__ void softmax_kernel(float* __restrict__ sc){
  int row = blockIdx.x;           // 0..TT-1
  int bh  = blockIdx.y;           // 0..BB*NH-1
  float* s = sc + ((long)bh*TT + row)*TT;
  int n = row + 1;
  float m = -3.0e38f;
  for (int j = threadIdx.x; j < n; j += blockDim.x) m = fmaxf(m, s[j]);
  m = blockMax(m);
  float sum = 0.f;
  for (int j = threadIdx.x; j < n; j += blockDim.x){
    float e = expf(s[j] - m);
    s[j] = e; sum += e;
  }
  sum = blockSum(sum);
  float inv = 1.f / sum;
  for (int j = threadIdx.x; j < TT; j += blockDim.x)
    s[j] = (j < n) ? s[j]*inv : 0.f;
}

// ---------------- SGEMM ----------------
// C[M,N] = epi( alpha * A[M,K] @ B , bias, C )
// TRANSB=false: B stored [K,N] (ldb = row stride). TRANSB=true: B stored [N,K].
// Batched over blockIdx.z with two-component strides: off = (z/NH)*s1 + (z%NH)*s2.
// EPI: 0 none, 1 +bias, 2 +bias + C(in-place residual), 3 gelu(acc+bias)
// Requires: BM=128, BK=8, BN in {64,128}, 256 threads, K % 8 == 0.
template<int BM,int BN,int BK,int TM,int TN,bool TRANSB,int EPI>
__global__ void __launch_bounds__(256)
sgemm_kernel(int M, int N, int K, float alpha,
             const float* __restrict__ A, int lda, long sA1, long sA2,
             const float* __restrict__ B, int ldb, long sB1, long sB2,
             float* __restrict__ C, int ldc, long sC1, long sC2,
             const float* __restrict__ bias)
{
  int z  = blockIdx.z;
  int zb = z / NH, zh = z % NH;
  A += (long)zb*sA1 + (long)zh*sA2;
  B += (long)zb*sB1 + (long)zh*sB2;
  C += (long)zb*sC1 + (long)zh*sC2;

  __shared__ float As[BK][BM];
  __shared__ float Bs[BK][BN];

  const int tid = threadIdx.x;
  const int m0 = blockIdx.y * BM;
  const int n0 = blockIdx.x * BN;
  const int tnx = tid % (BN/TN);
  const int tny = tid / (BN/TN);

  float acc[TM][TN];
#pragma unroll
  for (int i=0;i<TM;i++)
#pragma unroll
    for (int j=0;j<TN;j++) acc[i][j]=0.f;

  for (int kt = 0; kt < K; kt += BK) {
    // ---- load A tile (128x8): one float4 per thread ----
    {
      int row = tid >> 1;
      int kk  = (tid & 1) * 4;
      float4 av = make_float4(0.f,0.f,0.f,0.f);
      if (m0 + row < M)
        av = *reinterpret_cast<const float4*>(&A[(long)(m0+row)*lda + kt + kk]);
      As[kk+0][row]=av.x; As[kk+1][row]=av.y; As[kk+2][row]=av.z; As[kk+3][row]=av.w;
    }
    // ---- load B tile ----
    if (!TRANSB) {
      constexpr int NF4 = BN*BK/4;   // 256 or 128
      if (NF4 == 256 || tid < NF4) {
        int k = tid / (BN/4);
        int n = (tid % (BN/4)) * 4;
        float4 bv;
        if (n0 + n + 3 < N) {
          bv = *reinterpret_cast<const float4*>(&B[(long)(kt+k)*ldb + n0 + n]);
        } else {
          float t0 = (n0+n+0 < N) ? B[(long)(kt+k)*ldb + n0+n+0] : 0.f;
          float t1 = (n0+n+1 < N) ? B[(long)(kt+k)*ldb + n0+n+1] : 0.f;
          float t2 = (n0+n+2 < N) ? B[(long)(kt+k)*ldb + n0+n+2] : 0.f;
          float t3 = (n0+n+3 < N) ? B[(long)(kt+k)*ldb + n0+n+3] : 0.f;
          bv = make_float4(t0,t1,t2,t3);
        }
        Bs[k][n+0]=bv.x; Bs[k][n+1]=bv.y; Bs[k][n+2]=bv.z; Bs[k][n+3]=bv.w;
      }
    } else {
      constexpr int NF4 = BN*BK/4;
      if (NF4 == 256 || tid < NF4) {
        int n  = tid >> 1;
        int kk = (tid & 1) * 4;
        float4 bv = make_float4(0.f,0.f,0.f,0.f);
        if (n0 + n < N)
          bv = *reinterpret_cast<const float4*>(&B[(long)(n0+n)*ldb + kt + kk]);
        Bs[kk+0][n]=bv.x; Bs[kk+1][n]=bv.y; Bs[kk+2][n]=bv.z; Bs[kk+3][n]=bv.w;
      }
    }
    __syncthreads();

    // ---- compute ----
#pragma unroll
    for (int kk = 0; kk < BK; kk++) {
      float ar[TM], br[TN];
      *reinterpret_cast<float4*>(&ar[0]) = *reinterpret_cast<const float4*>(&As[kk][tny*TM]);
      *reinterpret_cast<float4*>(&ar[4]) = *reinterpret_cast<const float4*>(&As[kk][tny*TM+4]);
      *reinterpret_cast<float4*>(&br[0]) = *reinterpret_cast<const float4*>(&Bs[kk][tnx*TN]);
      if (TN == 8)
        *reinterpret_cast<float4*>(&br[4]) = *reinterpret_cast<const float4*>(&Bs[kk][tnx*TN+4]);
#pragma unroll
      for (int i=0;i<TM;i++)
#pragma unroll
        for (int j=0;j<TN;j++)
          acc[i][j] = fmaf(ar[i], br[j], acc[i][j]);
    }
    __syncthreads();
  }

  // ---- epilogue ----
#pragma unroll
  for (int i=0;i<TM;i++){
    int row = m0 + tny*TM + i;
    if (row >= M) continue;
#pragma unroll
    for (int j=0;j<TN;j++){
      int col = n0 + tnx*TN + j;
      if (col >= N) continue;
      float v = alpha * acc[i][j];
      if (EPI == 1) v += bias[col];
      if (EPI == 2) v += bias[col] + C[(long)row*ldc + col];
      if (EPI == 3) { v += bias[col]; v = 0.5f*v*(1.f + erff(v*0.70710678118654752f)); }
      C[(long)row*ldc + col] = v;
    }
  }
}

// ---------------- host ----------------
extern "C" void kernel_launch(void* const* d_in, const int* in_sizes, int n_in,
                              void* d_out, int out_size) {
  const int*   idx  = (const int*  )d_in[0];
  const float* tokW = (const float*)d_in[1];
  const float* posW = (const float*)d_in[2];
  const float* ln1g = (const float*)d_in[3];
  const float* ln1b = (const float*)d_in[4];
  const float* Wq   = (const float*)d_in[5];
  const float* Wk   = (const float*)d_in[6];
  const float* Wv   = (const float*)d_in[7];
  const float* Wo   = (const float*)d_in[8];
  const float* bo   = (const float*)d_in[9];
  const float* ln2g = (const float*)d_in[10];
  const float* ln2b = (const float*)d_in[11];
  const float* W1   = (const float*)d_in[12];
  const float* b1   = (const float*)d_in[13];
  const float* W2   = (const float*)d_in[14];
  const float* b2   = (const float*)d_in[15];
  const float* lnfg = (const float*)d_in[16];
  const float* lnfb = (const float*)d_in[17];
  float* out = (float*)d_out;

  float *x,*h,*q,*k,*v,*att,*ff,*sc;
  cudaGetSymbolAddress((void**)&x,   g_x);
  cudaGetSymbolAddress((void**)&h,   g_h);
  cudaGetSymbolAddress((void**)&q,   g_q);
  cudaGetSymbolAddress((void**)&k,   g_k);
  cudaGetSymbolAddress((void**)&v,   g_v);
  cudaGetSymbolAddress((void**)&att, g_att);
  cudaGetSymbolAddress((void**)&ff,  g_ff);
  cudaGetSymbolAddress((void**)&sc,  g_sc);

  embed_kernel<<<BT, 256>>>(idx, tokW, posW, x);

  const dim3 gDD (DD/128,  BT/128, 1);     // [BT x DD]  GEMMs
  const dim3 gFF (FF/128,  BT/128, 1);     // [BT x 4D]
  const dim3 gSC (TT/128,  TT/128, BB*NH); // scores
  const dim3 gAV (1,       TT/128, BB*NH); // att @ V  (N=64 tile)
  const dim3 gLM ((VV+127)/128, BT/128, 1);

  for (int l = 0; l < NL; l++) {
    long lDD  = (long)l*DD;
    long lDD2 = (long)l*DD*DD;
    long lDF  = (long)l*DD*FF;
    long lF   = (long)l*FF;

    ln_kernel<<<BT, 256>>>(x, h, ln1g + lDD, ln1b + lDD);

    sgemm_kernel<128,128,8,8,8,false,0><<<gDD,256>>>(BT, DD, DD, 1.f,
        h, DD,0,0,  Wq + lDD2, DD,0,0,  q, DD,0,0, nullptr);
    sgemm_kernel<128,128,8,8,8,false,0><<<gDD,256>>>(BT, DD, DD, 1.f,
        h, DD,0,0,  Wk + lDD2, DD,0,0,  k, DD,0,0, nullptr);
    sgemm_kernel<128,128,8,8,8,false,0><<<gDD,256>>>(BT, DD, DD, 1.f,
        h, DD,0,0,  Wv + lDD2, DD,0,0,  v, DD,0,0, nullptr);

    // scores[b,h] = 0.125 * q_slice @ k_slice^T   (NT, K=64)
    sgemm_kernel<128,128,8,8,8,true,0><<<gSC,256>>>(TT, TT, HDIM, 0.125f,
        q,  DD, (long)TT*DD, HDIM,
        k,  DD, (long)TT*DD, HDIM,
        sc, TT, (long)NH*TT*TT, (long)TT*TT, nullptr);

    softmax_kernel<<<dim3(TT, BB*NH), 256>>>(sc);

    // att[b,h] = wei @ v_slice   (NN, N=64)
    sgemm_kernel<128,64,8,8,4,false,0><<<gAV,256>>>(TT, HDIM, TT, 1.f,
        sc,  TT, (long)NH*TT*TT, (long)TT*TT,
        v,   DD, (long)TT*DD, HDIM,
        att, DD, (long)TT*DD, HDIM, nullptr);

    // x += att @ Wo + bo
    sgemm_kernel<128,128,8,8,8,false,2><<<gDD,256>>>(BT, DD, DD, 1.f,
        att, DD,0,0,  Wo + lDD2, DD,0,0,  x, DD,0,0, bo + lDD);

    ln_kernel<<<BT, 256>>>(x, h, ln2g + lDD, ln2b + lDD);

    // ff = gelu(h @ W1 + b1)
    sgemm_kernel<128,128,8,8,8,false,3><<<gFF,256>>>(BT, FF, DD, 1.f,
        h, DD,0,0,  W1 + lDF, FF,0,0,  ff, FF,0,0, b1 + lF);

    // x += ff @ W2 + b2
    sgemm_kernel<128,128,8,8,8,false,2><<<gDD,256>>>(BT, DD, FF, 1.f,
        ff, FF,0,0,  W2 + lDF, DD,0,0,  x, DD,0,0, b2 + lDD);
  }

  ln_kernel<<<BT, 256>>>(x, h, lnfg, lnfb);

  // logits = h @ tokW^T  (NT, N edge at 50257)
  sgemm_kernel<128,128,8,8,8,true,0><<<gLM,256>>>(BT, VV, DD, 1.f,
      h, DD,0,0,  tokW, DD,0,0,  out, VV,0,0, nullptr);
}

// round 3
// speedup vs baseline: 2.4842x; 2.4842x over previous
#include <cuda_runtime.h>
#include <cuda_bf16.h>
#include <math.h>

#define BB 2
#define TT 1024
#define DD 1024
#define NH 16
#define HDIM 64
#define NL 6
#define VV 50257
#define FF (4*DD)
#define LNEPS 1e-5f
#define BT (BB*TT)

// ---------------- scratch (device globals: allocation-free rule) ----------------
__device__ float g_x  [BT*DD];
__device__ float g_h  [BT*DD];
__device__ float g_q  [BT*DD];
__device__ float g_k  [BT*DD];
__device__ float g_v  [BT*DD];
__device__ float g_att[BT*DD];
__device__ float g_ff [BT*FF];
__device__ float g_sc [(long)BB*NH*TT*TT];

// ---------------- reductions ----------------
__device__ __forceinline__ float warpSum(float v){
#pragma unroll
  for (int o=16;o;o>>=1) v += __shfl_xor_sync(0xffffffffu, v, o);
  return v;
}
__device__ __forceinline__ float warpMax(float v){
#pragma unroll
  for (int o=16;o;o>>=1) v = fmaxf(v, __shfl_xor_sync(0xffffffffu, v, o));
  return v;
}
__device__ float blockSum(float v){
  __shared__ float sh[8];
  __syncthreads();
  int lane = threadIdx.x & 31, w = threadIdx.x >> 5;
  v = warpSum(v);
  if (lane == 0) sh[w] = v;
  __syncthreads();
  if (w == 0) {
    v = (lane < (int)(blockDim.x>>5)) ? sh[lane] : 0.f;
    v = warpSum(v);
    if (lane == 0) sh[0] = v;
  }
  __syncthreads();
  return sh[0];
}
__device__ float blockMax(float v){
  __shared__ float sh[8];
  __syncthreads();
  int lane = threadIdx.x & 31, w = threadIdx.x >> 5;
  v = warpMax(v);
  if (lane == 0) sh[w] = v;
  __syncthreads();
  if (w == 0) {
    v = (lane < (int)(blockDim.x>>5)) ? sh[lane] : -3.0e38f;
    v = warpMax(v);
    if (lane == 0) sh[0] = v;
  }
  __syncthreads();
  return sh[0];
}

// ---------------- embed ----------------
__global__ void embed_kernel(const int* __restrict__ idx,
                             const float* __restrict__ tokW,
                             const float* __restrict__ posW,
                             float* __restrict__ x){
  int i = blockIdx.x;
  int t = i % TT;
  long tok = idx[i];
  const float* tw = tokW + tok*DD;
  const float* pw = posW + (long)t*DD;
  float* xr = x + (long)i*DD;
  for (int d = threadIdx.x; d < DD; d += blockDim.x)
    xr[d] = tw[d] + pw[d];
}

// ---------------- layernorm ----------------
__global__ void ln_kernel(const float* __restrict__ x, float* __restrict__ y,
                          const float* __restrict__ g, const float* __restrict__ b){
  int row = blockIdx.x;
  const float* xr = x + (long)row*DD;
  float s = 0.f, ss = 0.f;
  for (int d = threadIdx.x; d < DD; d += blockDim.x){
    float v = xr[d]; s += v; ss += v*v;
  }
  s = blockSum(s);
  ss = blockSum(ss);
  float mean = s * (1.f/DD);
  float var  = ss * (1.f/DD) - mean*mean;
  float rstd = rsqrtf(var + LNEPS);
  float* yr = y + (long)row*DD;
  for (int d = threadIdx.x; d < DD; d += blockDim.x)
    yr[d] = (xr[d] - mean) * rstd * g[d] + b[d];
}

// ---------------- causal softmax (in place on scores) ----------------
__global__ void softmax_kernel(float* __restrict__ sc){
  int row = blockIdx.x;
  int bh  = blockIdx.y;
  float* s = sc + ((long)bh*TT + row)*TT;
  int n = row + 1;
  float m = -3.0e38f;
  for (int j = threadIdx.x; j < n; j += blockDim.x) m = fmaxf(m, s[j]);
  m = blockMax(m);
  float sum = 0.f;
  for (int j = threadIdx.x; j < n; j += blockDim.x){
    float e = expf(s[j] - m);
    s[j] = e; sum += e;
  }
  sum = blockSum(sum);
  float inv = 1.f / sum;
  for (int j = threadIdx.x; j < TT; j += blockDim.x)
    s[j] = (j < n) ? s[j]*inv : 0.f;
}

// ---------------- bf16x3 tensor-core GEMM ----------------
// C[M,N] = epi( alpha * A[M,K] @ B , bias, C ),  fp32 in/out, split-bf16 compute.
// TRANSB=false: B stored [K,N]; TRANSB=true: B stored [N,K].
// Batched over blockIdx.z: off = (z/NH)*s1 + (z%NH)*s2.
// EPI: 0 none, 2 +bias + C(in-place residual), 3 gelu(acc+bias)
// Tiles: BM=BN=128, BK=16, 256 threads (8 warps, 64x32 warp tiles).
// Requires: M % 128 == 0, K % 16 == 0. N guarded.

__device__ __forceinline__ void split2(float x0, float x1, unsigned &h, unsigned &l){
  __nv_bfloat16 h0 = __float2bfloat16_rn(x0);
  __nv_bfloat16 h1 = __float2bfloat16_rn(x1);
  __nv_bfloat16 l0 = __float2bfloat16_rn(x0 - __bfloat162float(h0));
  __nv_bfloat16 l1 = __float2bfloat16_rn(x1 - __bfloat162float(h1));
  h = (unsigned)__bfloat16_as_ushort(h0) | ((unsigned)__bfloat16_as_ushort(h1) << 16);
  l = (unsigned)__bfloat16_as_ushort(l0) | ((unsigned)__bfloat16_as_ushort(l1) << 16);
}

__device__ __forceinline__ void ldsm4(unsigned r[4], const void* p){
  unsigned a = (unsigned)__cvta_generic_to_shared(p);
  asm volatile("ldmatrix.sync.aligned.m8n8.x4.shared.b16 {%0,%1,%2,%3}, [%4];"
    : "=r"(r[0]),"=r"(r[1]),"=r"(r[2]),"=r"(r[3]) : "r"(a));
}
__device__ __forceinline__ void ldsm4t(unsigned &r0, unsigned &r1, unsigned &r2, unsigned &r3, const void* p){
  unsigned a = (unsigned)__cvta_generic_to_shared(p);
  asm volatile("ldmatrix.sync.aligned.m8n8.x4.trans.shared.b16 {%0,%1,%2,%3}, [%4];"
    : "=r"(r0),"=r"(r1),"=r"(r2),"=r"(r3) : "r"(a));
}
__device__ __forceinline__ void mma16816(float d[4], const unsigned a[4], const unsigned b[2]){
  asm volatile("mma.sync.aligned.m16n8k16.row.col.f32.bf16.bf16.f32 "
    "{%0,%1,%2,%3}, {%4,%5,%6,%7}, {%8,%9}, {%0,%1,%2,%3};"
    : "+f"(d[0]),"+f"(d[1]),"+f"(d[2]),"+f"(d[3])
    : "r"(a[0]),"r"(a[1]),"r"(a[2]),"r"(a[3]), "r"(b[0]),"r"(b[1]));
}

template<bool TRANSB, int EPI>
__global__ void __launch_bounds__(256)
bgemm_kernel(int M, int N, int K, float alpha,
             const float* __restrict__ A, int lda, long sA1, long sA2,
             const float* __restrict__ B, int ldb, long sB1, long sB2,
             float* __restrict__ C, int ldc, long sC1, long sC2,
             const float* __restrict__ bias)
{
  // padded strides: As row = 24 bf16 (48B -> 3r%8 distinct for ldmatrix),
  // Bs row = 136 bf16 (272B -> 17r%8 distinct)
  __shared__ __nv_bfloat16 As[2][2][128][24];   // [buf][plane][m][k]
  __shared__ __nv_bfloat16 Bs[2][2][16][136];   // [buf][plane][k][n]

  int z  = blockIdx.z;
  int zb = z / NH, zh = z % NH;
  A += (long)zb*sA1 + (long)zh*sA2;
  B += (long)zb*sB1 + (long)zh*sB2;
  C += (long)zb*sC1 + (long)zh*sC2;

  const int tid = threadIdx.x;
  const int m0 = blockIdx.y * 128;
  const int n0 = blockIdx.x * 128;

  // loader indices
  const int arow = tid >> 2;           // 0..63 (and +64)
  const int akc  = (tid & 3) << 2;     // 0,4,8,12
  const int bk   = tid >> 5;           // 0..7 (and +8)   (NN)
  const int bc   = (tid & 31) << 2;    // 0..124          (NN)
  const int tn   = tid & 127;          // 0..127          (TT)
  const int tkh  = (tid >> 7) << 3;    // 0 or 8          (TT)

  // compute indices
  const int warp = tid >> 5, lane = tid & 31;
  const int wm = warp >> 2, wn = warp & 3;     // warp grid 2x4
  const int lrow = lane & 15;
  const int lcol = (lane >> 4) << 3;           // 0 or 8

  float4 pA0, pA1, pB0, pB1;

#define PREF_A(kt) { \
    pA0 = *(const float4*)&A[(long)(m0+arow)*lda + (kt) + akc]; \
    pA1 = *(const float4*)&A[(long)(m0+arow+64)*lda + (kt) + akc]; }

#define STORE_A(bf) { \
    unsigned h_, l_; \
    split2(pA0.x,pA0.y,h_,l_); *(unsigned*)&As[bf][0][arow][akc]=h_;      *(unsigned*)&As[bf][1][arow][akc]=l_; \
    split2(pA0.z,pA0.w,h_,l_); *(unsigned*)&As[bf][0][arow][akc+2]=h_;    *(unsigned*)&As[bf][1][arow][akc+2]=l_; \
    split2(pA1.x,pA1.y,h_,l_); *(unsigned*)&As[bf][0][arow+64][akc]=h_;   *(unsigned*)&As[bf][1][arow+64][akc]=l_; \
    split2(pA1.z,pA1.w,h_,l_); *(unsigned*)&As[bf][0][arow+64][akc+2]=h_; *(unsigned*)&As[bf][1][arow+64][akc+2]=l_; }

#define PREF_B(kt) { \
    if (!TRANSB) { \
      if (n0 + bc + 3 < N) { \
        pB0 = *(const float4*)&B[(long)((kt)+bk)*ldb + n0 + bc]; \
        pB1 = *(const float4*)&B[(long)((kt)+bk+8)*ldb + n0 + bc]; \
      } else { \
        const float* r0_ = &B[(long)((kt)+bk)*ldb]; \
        const float* r1_ = &B[(long)((kt)+bk+8)*ldb]; \
        pB0.x = (n0+bc+0<N)?r0_[n0+bc+0]:0.f; pB0.y = (n0+bc+1<N)?r0_[n0+bc+1]:0.f; \
        pB0.z = (n0+bc+2<N)?r0_[n0+bc+2]:0.f; pB0.w = (n0+bc+3<N)?r0_[n0+bc+3]:0.f; \
        pB1.x = (n0+bc+0<N)?r1_[n0+bc+0]:0.f; pB1.y = (n0+bc+1<N)?r1_[n0+bc+1]:0.f; \
        pB1.z = (n0+bc+2<N)?r1_[n0+bc+2]:0.f; pB1.w = (n0+bc+3<N)?r1_[n0+bc+3]:0.f; \
      } \
    } else { \
      if (n0 + tn < N) { \
        pB0 = *(const float4*)&B[(long)(n0+tn)*ldb + (kt) + tkh]; \
        pB1 = *(const float4*)&B[(long)(n0+tn)*ldb + (kt) + tkh + 4]; \
      } else { \
        pB0 = make_float4(0.f,0.f,0.f,0.f); pB1 = pB0; \
      } \
    } }

#define STORE_B(bf) { \
    if (!TRANSB) { \
      unsigned h_, l_; \
      split2(pB0.x,pB0.y,h_,l_); *(unsigned*)&Bs[bf][0][bk][bc]=h_;     *(unsigned*)&Bs[bf][1][bk][bc]=l_; \
      split2(pB0.z,pB0.w,h_,l_); *(unsigned*)&Bs[bf][0][bk][bc+2]=h_;   *(unsigned*)&Bs[bf][1][bk][bc+2]=l_; \
      split2(pB1.x,pB1.y,h_,l_); *(unsigned*)&Bs[bf][0][bk+8][bc]=h_;   *(unsigned*)&Bs[bf][1][bk+8][bc]=l_; \
      split2(pB1.z,pB1.w,h_,l_); *(unsigned*)&Bs[bf][0][bk+8][bc+2]=h_; *(unsigned*)&Bs[bf][1][bk+8][bc+2]=l_; \
    } else { \
      float v_[8] = {pB0.x,pB0.y,pB0.z,pB0.w,pB1.x,pB1.y,pB1.z,pB1.w}; \
      _Pragma("unroll") \
      for (int i_=0;i_<8;i_++){ \
        __nv_bfloat16 hh_ = __float2bfloat16_rn(v_[i_]); \
        Bs[bf][0][tkh+i_][tn] = hh_; \
        Bs[bf][1][tkh+i_][tn] = __float2bfloat16_rn(v_[i_] - __bfloat162float(hh_)); \
      } \
    } }

  float acc[4][4][4];
#pragma unroll
  for (int i=0;i<4;i++)
#pragma unroll
    for (int j=0;j<4;j++)
#pragma unroll
      for (int r=0;r<4;r++) acc[i][j][r]=0.f;

  const int NT = K >> 4;
  PREF_A(0); PREF_B(0);
  STORE_A(0); STORE_B(0);
  __syncthreads();

  for (int it = 0; it < NT; ++it) {
    const int bf = it & 1;
    const bool more = (it + 1) < NT;
    if (more) { PREF_A((it+1)<<4); PREF_B((it+1)<<4); }

    unsigned Ah[4][4], Al[4][4], Bh[4][2], Bl[4][2];
#pragma unroll
    for (int mi=0;mi<4;mi++){
      ldsm4(Ah[mi], &As[bf][0][wm*64 + mi*16 + lrow][lcol]);
      ldsm4(Al[mi], &As[bf][1][wm*64 + mi*16 + lrow][lcol]);
    }
#pragma unroll
    for (int np=0;np<2;np++){
      ldsm4t(Bh[2*np][0],Bh[2*np][1],Bh[2*np+1][0],Bh[2*np+1][1],
             &Bs[bf][0][lrow][wn*32 + np*16 + lcol]);
      ldsm4t(Bl[2*np][0],Bl[2*np][1],Bl[2*np+1][0],Bl[2*np+1][1],
             &Bs[bf][1][lrow][wn*32 + np*16 + lcol]);
    }
#pragma unroll
    for (int mi=0;mi<4;mi++)
#pragma unroll
      for (int ni=0;ni<4;ni++){
        mma16816(acc[mi][ni], Ah[mi], Bh[ni]);
        mma16816(acc[mi][ni], Al[mi], Bh[ni]);
        mma16816(acc[mi][ni], Ah[mi], Bl[ni]);
      }

    if (more) { STORE_A(!bf); STORE_B(!bf); }
    __syncthreads();
  }

  // ---- epilogue ----
  const int rb = m0 + wm*64 + (lane >> 2);
  const int cb = n0 + wn*32 + 2*(lane & 3);
#pragma unroll
  for (int mi=0;mi<4;mi++){
#pragma unroll
    for (int ni=0;ni<4;ni++){
      int c0 = cb + ni*8;
#pragma unroll
      for (int r=0;r<4;r++){
        int row = rb + mi*16 + ((r>>1)<<3);   // +8 for r=2,3
        int col = c0 + (r&1);
        if (col >= N) continue;
        float vv = alpha * acc[mi][ni][r];
        if (EPI == 2) vv += bias[col] + C[(long)row*ldc + col];
        if (EPI == 3) { vv += bias[col]; vv = 0.5f*vv*(1.f + erff(vv*0.70710678118654752f)); }
        C[(long)row*ldc + col] = vv;
      }
    }
  }
#undef PREF_A
#undef STORE_A
#undef PREF_B
#undef STORE_B
}

// ---------------- host ----------------
extern "C" void kernel_launch(void* const* d_in, const int* in_sizes, int n_in,
                              void* d_out, int out_size) {
  const int*   idx  = (const int*  )d_in[0];
  const float* tokW = (const float*)d_in[1];
  const float* posW = (const float*)d_in[2];
  const float* ln1g = (const float*)d_in[3];
  const float* ln1b = (const float*)d_in[4];
  const float* Wq   = (const float*)d_in[5];
  const float* Wk   = (const float*)d_in[6];
  const float* Wv   = (const float*)d_in[7];
  const float* Wo   = (const float*)d_in[8];
  const float* bo   = (const float*)d_in[9];
  const float* ln2g = (const float*)d_in[10];
  const float* ln2b = (const float*)d_in[11];
  const float* W1   = (const float*)d_in[12];
  const float* b1   = (const float*)d_in[13];
  const float* W2   = (const float*)d_in[14];
  const float* b2   = (const float*)d_in[15];
  const float* lnfg = (const float*)d_in[16];
  const float* lnfb = (const float*)d_in[17];
  float* out = (float*)d_out;

  float *x,*h,*q,*k,*v,*att,*ff,*sc;
  cudaGetSymbolAddress((void**)&x,   g_x);
  cudaGetSymbolAddress((void**)&h,   g_h);
  cudaGetSymbolAddress((void**)&q,   g_q);
  cudaGetSymbolAddress((void**)&k,   g_k);
  cudaGetSymbolAddress((void**)&v,   g_v);
  cudaGetSymbolAddress((void**)&att, g_att);
  cudaGetSymbolAddress((void**)&ff,  g_ff);
  cudaGetSymbolAddress((void**)&sc,  g_sc);

  embed_kernel<<<BT, 256>>>(idx, tokW, posW, x);

  const dim3 gDD (DD/128,  BT/128, 1);
  const dim3 gFF (FF/128,  BT/128, 1);
  const dim3 gSC (TT/128,  TT/128, BB*NH);
  const dim3 gAV (1,       TT/128, BB*NH);
  const dim3 gLM ((VV+127)/128, BT/128, 1);

  for (int l = 0; l < NL; l++) {
    long lDD  = (long)l*DD;
    long lDD2 = (long)l*DD*DD;
    long lDF  = (long)l*DD*FF;
    long lF   = (long)l*FF;

    ln_kernel<<<BT, 256>>>(x, h, ln1g + lDD, ln1b + lDD);

    bgemm_kernel<false,0><<<gDD,256>>>(BT, DD, DD, 1.f,
        h, DD,0,0,  Wq + lDD2, DD,0,0,  q, DD,0,0, nullptr);
    bgemm_kernel<false,0><<<gDD,256>>>(BT, DD, DD, 1.f,
        h, DD,0,0,  Wk + lDD2, DD,0,0,  k, DD,0,0, nullptr);
    bgemm_kernel<false,0><<<gDD,256>>>(BT, DD, DD, 1.f,
        h, DD,0,0,  Wv + lDD2, DD,0,0,  v, DD,0,0, nullptr);

    // scores[b,h] = 0.125 * q_slice @ k_slice^T   (K=64)
    bgemm_kernel<true,0><<<gSC,256>>>(TT, TT, HDIM, 0.125f,
        q,  DD, (long)TT*DD, HDIM,
        k,  DD, (long)TT*DD, HDIM,
        sc, TT, (long)NH*TT*TT, (long)TT*TT, nullptr);

    softmax_kernel<<<dim3(TT, BB*NH), 256>>>(sc);

    // att[b,h] = wei @ v_slice   (N=64, guarded)
    bgemm_kernel<false,0><<<gAV,256>>>(TT, HDIM, TT, 1.f,
        sc,  TT, (long)NH*TT*TT, (long)TT*TT,
        v,   DD, (long)TT*DD, HDIM,
        att, DD, (long)TT*DD, HDIM, nullptr);

    // x += att @ Wo + bo
    bgemm_kernel<false,2><<<gDD,256>>>(BT, DD, DD, 1.f,
        att, DD,0,0,  Wo + lDD2, DD,0,0,  x, DD,0,0, bo + lDD);

    ln_kernel<<<BT, 256>>>(x, h, ln2g + lDD, ln2b + lDD);

    // ff = gelu(h @ W1 + b1)
    bgemm_kernel<false,3><<<gFF,256>>>(BT, FF, DD, 1.f,
        h, DD,0,0,  W1 + lDF, FF,0,0,  ff, FF,0,0, b1 + lF);

    // x += ff @ W2 + b2
    bgemm_kernel<false,2><<<gDD,256>>>(BT, DD, FF, 1.f,
        ff, FF,0,0,  W2 + lDF, DD,0,0,  x, DD,0,0, b2 + lDD);
  }

  ln_kernel<<<BT, 256>>>(x, h, lnfg, lnfb);

  // logits = h @ tokW^T  (weight-tied)
  bgemm_kernel<true,0><<<gLM,256>>>(BT, VV, DD, 1.f,
      h, DD,0,0,  tokW, DD,0,0,  out, VV,0,0, nullptr);
}